// round 17
// baseline (speedup 1.0000x reference)
#include <cuda_runtime.h>
#include <stdint.h>

#define N_TRIALS   8
#define T_MS       2500
#define N_NEURONS  16000
#define N_SAMPLES  50
#define K_MAX      160
#define N_BINS     20
#define SYNC_COST  10.0f
#define EPS_F      1e-7f
#define SORT_N     256
#define NC         8            // neuron-space chunks (2000 neurons each)
#define MAXS       24           // max samples per trial (headroom over E[6.25])
#define TB         64           // t per block (2 per lane)

// round(logspace(-3,0,20)*1000), matching numpy exactly
__constant__ int c_bins[N_BINS] = {1,1,2,3,4,6,9,13,18,26,38,55,78,113,162,234,336,483,695,1000};

// scratch (no allocations allowed -> __device__ globals)
__device__ int   g_sidx[N_SAMPLES * K_MAX];        // per-sample ASCENDING active indices
__device__ int   g_soff[N_SAMPLES * (NC + 1)];     // per-sample chunk offsets into sorted list
__device__ float g_sel[N_SAMPLES * T_MS];
__device__ float g_fano_parts[N_BINS * N_SAMPLES];
__device__ int   g_done_ctr;                       // zero-init; last fano block resets

// ---------------------------------------------------------------------------
// Kernel 0: per sample, bitonic sort its cnt active indices ascending
// (exact: 0/1 summands are order-independent), then chunk offsets by
// binary search at neuron thresholds c*2000.
// ---------------------------------------------------------------------------
__global__ void __launch_bounds__(SORT_N) sort_prep_kernel(const int* __restrict__ idx,
                                                           const int* __restrict__ counts)
{
    const int s   = blockIdx.x;
    const int tid = threadIdx.x;
    const int cnt = counts[s];

    __shared__ int a[SORT_N];
    a[tid] = (tid < cnt) ? idx[s * K_MAX + tid] : 0x7FFFFFFF;
    __syncthreads();

    for (int k = 2; k <= SORT_N; k <<= 1) {
        for (int j = k >> 1; j > 0; j >>= 1) {
            const int ixj = tid ^ j;
            if (ixj > tid) {
                const bool up = ((tid & k) == 0);
                const int x = a[tid], y = a[ixj];
                if ((x > y) == up) { a[tid] = y; a[ixj] = x; }
            }
            __syncthreads();
        }
    }

    if (tid < K_MAX)
        g_sidx[s * K_MAX + tid] = (tid < cnt) ? a[tid] : 0;

    // chunk offsets: lower_bound(a[0..cnt), c * (N_NEURONS/NC))
    if (tid <= NC) {
        const int thr = tid * (N_NEURONS / NC);
        int lo = 0, hi = cnt;
        while (lo < hi) {
            const int mid = (lo + hi) >> 1;
            if (a[mid] < thr) lo = mid + 1; else hi = mid;
        }
        g_soff[s * (NC + 1) + tid] = lo;
    }
}

// ---------------------------------------------------------------------------
// Kernel 1: sel. Block = (trial r, 64 consecutive t) x 8 warp-slots.
// Lane covers t0+lane and t0+32+lane: each smem index feeds TWO row loads
// (8 outstanding LDGs per unroll iter). Chunk-lockstep over NC neuron
// windows preserved (proven line-dedup property).
// ---------------------------------------------------------------------------
__global__ void __launch_bounds__(256) sel_kernel(const float* __restrict__ spikes,
                                                  const int*   __restrict__ trials,
                                                  const int*   __restrict__ counts)
{
    const int r   = blockIdx.y;
    const int t0  = blockIdx.x * TB;
    const int tid = threadIdx.x;
    const int lane = tid & 31;
    const int w    = tid >> 5;

    __shared__ uint16_t lists[MAXS][K_MAX];   // 7.7 KB
    __shared__ int      soff_s[MAXS][NC + 1];
    __shared__ int      sids[MAXS];
    __shared__ int      sc_s;

    if (tid == 0) {
        int c = 0;
        for (int s = 0; s < N_SAMPLES; s++)
            if (trials[s] == r && c < MAXS) sids[c++] = s;
        sc_s = c;
    }
    __syncthreads();
    const int sc = sc_s;
    if (sc == 0) return;

    for (int p = tid; p < sc * K_MAX; p += 256) {
        const int si = p / K_MAX, k = p % K_MAX;
        lists[si][k] = (uint16_t)g_sidx[sids[si] * K_MAX + k];
    }
    for (int p = tid; p < sc * (NC + 1); p += 256) {
        const int si = p / (NC + 1), c = p % (NC + 1);
        soff_s[si][c] = g_soff[sids[si] * (NC + 1) + c];
    }
    __syncthreads();

    const int  tA      = t0 + lane;
    const int  tBt     = t0 + 32 + lane;
    const bool actA    = (tA  < T_MS);
    const bool actB    = (tBt < T_MS);
    const float* __restrict__ rowA =
        spikes + ((long long)r * T_MS + tA)  * (long long)N_NEURONS;
    const float* __restrict__ rowB =
        spikes + ((long long)r * T_MS + tBt) * (long long)N_NEURONS;

    float a0s = 0.f, a1s = 0.f, a2s = 0.f;   // row A accumulators per slot
    float b0s = 0.f, b1s = 0.f, b2s = 0.f;   // row B accumulators per slot

    #pragma unroll 1
    for (int c = 0; c < NC; c++) {
        #pragma unroll
        for (int slot = 0; slot < 3; slot++) {
            const int si = w + slot * 8;
            if (si >= sc) continue;
            const uint16_t* __restrict__ L = &lists[si][0];
            int j = soff_s[si][c];
            const int j1 = soff_s[si][c + 1];

            float pa0=0.f,pa1=0.f,pa2=0.f,pa3=0.f;
            float pb0=0.f,pb1=0.f,pb2=0.f,pb3=0.f;
            if (actA && actB) {
                for (; j + 4 <= j1; j += 4) {
                    const int n0=L[j+0], n1=L[j+1], n2=L[j+2], n3=L[j+3];
                    pa0 += rowA[n0]; pa1 += rowA[n1]; pa2 += rowA[n2]; pa3 += rowA[n3];
                    pb0 += rowB[n0]; pb1 += rowB[n1]; pb2 += rowB[n2]; pb3 += rowB[n3];
                }
                for (; j < j1; j++) { pa0 += rowA[L[j]]; pb0 += rowB[L[j]]; }
            } else if (actA) {
                for (; j + 4 <= j1; j += 4) {
                    pa0 += rowA[L[j+0]]; pa1 += rowA[L[j+1]];
                    pa2 += rowA[L[j+2]]; pa3 += rowA[L[j+3]];
                }
                for (; j < j1; j++) pa0 += rowA[L[j]];
            }
            const float xa = (pa0+pa1)+(pa2+pa3);
            const float xb = (pb0+pb1)+(pb2+pb3);
            if (slot == 0)      { a0s += xa; b0s += xb; }
            else if (slot == 1) { a1s += xa; b1s += xb; }
            else                { a2s += xa; b2s += xb; }
        }
        __syncthreads();   // lockstep: all warps stay in the same neuron window
    }

    if (w < sc) {
        if (actA) g_sel[sids[w] * T_MS + tA ] = a0s;   // exact ints
        if (actB) g_sel[sids[w] * T_MS + tBt] = b0s;
    }
    if (w + 8 < sc) {
        if (actA) g_sel[sids[w + 8] * T_MS + tA ] = a1s;
        if (actB) g_sel[sids[w + 8] * T_MS + tBt] = b1s;
    }
    if (w + 16 < sc) {
        if (actA) g_sel[sids[w + 16] * T_MS + tA ] = a2s;
        if (actB) g_sel[sids[w + 16] * T_MS + tBt] = b2s;
    }
}

// ---------------------------------------------------------------------------
// Kernel 2: fano (block per sample, smem row, warp per bin) + fused loss:
// the LAST block to finish (atomic counter, deterministic output) computes
// the final scalar. Counter self-resets for graph replay.
// ---------------------------------------------------------------------------
__global__ void __launch_bounds__(640) fano_loss_kernel(const float* __restrict__ exp_fanos,
                                                        float* __restrict__ out)
{
    const int s    = blockIdx.x;
    const int tid  = threadIdx.x;
    const int b    = tid >> 5;       // warp id = bin
    const int lane = tid & 31;

    __shared__ float row[T_MS];      // 10 KB
    __shared__ int   is_last;

    const float* __restrict__ grow = g_sel + s * T_MS;
    for (int t = tid; t < T_MS; t += 640)
        row[t] = grow[t];
    __syncthreads();

    const int bs  = c_bins[b];
    const int nb  = T_MS / bs;
    const int lim = nb * bs;

    // pass 1: total sum over [0, nb*bs) — exact integers
    float tot = 0.f;
    for (int i = lane; i < lim; i += 32) tot += row[i];
    #pragma unroll
    for (int o = 16; o > 0; o >>= 1)
        tot += __shfl_xor_sync(0xFFFFFFFFu, tot, o);
    const float mean = tot / (float)nb;

    // pass 2: per-lane bins, accumulate squared deviations
    float ssq = 0.f;
    for (int j = lane; j < nb; j += 32) {
        const int base = j * bs;
        float p0=0.f, p1=0.f, p2=0.f, p3=0.f;
        int i = 0;
        for (; i + 4 <= bs; i += 4) {
            p0 += row[base + i + 0];
            p1 += row[base + i + 1];
            p2 += row[base + i + 2];
            p3 += row[base + i + 3];
        }
        float acc = (p0+p1)+(p2+p3);
        for (; i < bs; i++) acc += row[base + i];
        const float d = acc - mean;
        ssq += d * d;
    }
    #pragma unroll
    for (int o = 16; o > 0; o >>= 1)
        ssq += __shfl_xor_sync(0xFFFFFFFFu, ssq, o);

    if (lane == 0) {
        const float var = ssq / (float)nb;
        g_fano_parts[b * N_SAMPLES + s] = var / fmaxf(mean, EPS_F);
    }
    __syncthreads();

    // last-block election (deterministic result: reads after all writes)
    if (tid == 0) {
        __threadfence();
        const int prev = atomicAdd(&g_done_ctr, 1);
        is_last = (prev == N_SAMPLES - 1);
    }
    __syncthreads();

    if (is_last) {
        __threadfence();
        __shared__ float sq[N_BINS];

        const int w2 = b;      // warp per bin again
        float v = 0.f;
        if (lane < N_SAMPLES)      v += g_fano_parts[w2 * N_SAMPLES + lane];
        if (lane + 32 < N_SAMPLES) v += g_fano_parts[w2 * N_SAMPLES + lane + 32];
        #pragma unroll
        for (int o = 16; o > 0; o >>= 1)
            v += __shfl_down_sync(0xFFFFFFFFu, v, o);
        if (lane == 0) {
            const float fano = v / (float)N_SAMPLES;
            const float d = exp_fanos[w2] - fano;
            sq[w2] = d * d;
        }
        __syncthreads();

        if (w2 == 0) {
            float x = (lane < N_BINS) ? sq[lane] : 0.f;
            #pragma unroll
            for (int o = 16; o > 0; o >>= 1)
                x += __shfl_down_sync(0xFFFFFFFFu, x, o);
            if (lane == 0) {
                out[0] = SYNC_COST * (x / (float)N_BINS);
                g_done_ctr = 0;            // reset for next graph replay
            }
        }
    }
}

// ---------------------------------------------------------------------------
extern "C" void kernel_launch(void* const* d_in, const int* in_sizes, int n_in,
                              void* d_out, int out_size)
{
    const float* spikes    = (const float*)d_in[0];
    const float* exp_fanos = (const float*)d_in[1];
    const int*   trials    = (const int*)  d_in[2];
    const int*   idx       = (const int*)  d_in[3];
    const int*   counts    = (const int*)  d_in[4];
    float*       out       = (float*)d_out;

    sort_prep_kernel<<<N_SAMPLES, SORT_N>>>(idx, counts);

    dim3 g1((T_MS + TB - 1) / TB, N_TRIALS);   // (40, 8)
    sel_kernel<<<g1, 256>>>(spikes, trials, counts);

    fano_loss_kernel<<<N_SAMPLES, 640>>>(exp_fanos, out);
}